// round 7
// baseline (speedup 1.0000x reference)
#include <cuda_runtime.h>
#include <cuda_bf16.h>
#include <cstdint>

#define CC 64
#define MAXB 64

// ---------------- device scratch (no allocations allowed) ----------------
__device__ float g_sums[MAXB * CC];
__device__ __align__(16) float g_c[MAXB * CC];        // per-segment fused bias (BN folded)
__device__ __align__(16) uint32_t g_Wfrag[4096];      // B frags: uint4 = {hi_b0, hi_b1, lo_b0, lo_b1}

__device__ __forceinline__ uint32_t smem_u32(const void* p) {
    uint32_t a;
    asm("{ .reg .u64 t; cvta.to.shared.u64 t, %1; cvt.u32.u64 %0, t; }" : "=r"(a) : "l"(p));
    return a;
}

// ---------------- pass 0: zero sums ----------------
__global__ void k_zero(int n) {
    int i = blockIdx.x * blockDim.x + threadIdx.x;
    if (i < n) g_sums[i] = 0.f;
}

// ---------------- pass 1: segment sums (float4, MLP=8, smem tree, few atomics) ----------------
__global__ void k_segsum(const float4* __restrict__ x4, const int* __restrict__ o,
                         int N, int Bseg) {
    __shared__ int so[MAXB];
    __shared__ float4 red[256];
    int t = threadIdx.x;
    if (t < Bseg) so[t] = o[t];
    __syncthreads();
    int c4 = t & 15, rg = t >> 4;
    int rpb = (N + gridDim.x - 1) / gridDim.x;
    int r0 = blockIdx.x * rpb;
    if (r0 >= N) return;
    int r1 = min(N, r0 + rpb);
    int s0 = 0; while (s0 < Bseg - 1 && r0 >= so[s0]) s0++;
    int s1 = s0; while (s1 < Bseg - 1 && (r1 - 1) >= so[s1]) s1++;
    if (s0 == s1) {
        float4 a[8];
        #pragma unroll
        for (int q = 0; q < 8; q++) a[q] = make_float4(0.f, 0.f, 0.f, 0.f);
        int row = r0 + rg;
        for (; row + 112 < r1; row += 128) {
            #pragma unroll
            for (int q = 0; q < 8; q++) {
                float4 v = __ldcs(&x4[(size_t)(row + 16 * q) * 16 + c4]);
                a[q].x += v.x; a[q].y += v.y; a[q].z += v.z; a[q].w += v.w;
            }
        }
        for (; row < r1; row += 16) {
            float4 v = __ldcs(&x4[(size_t)row * 16 + c4]);
            a[0].x += v.x; a[0].y += v.y; a[0].z += v.z; a[0].w += v.w;
        }
        #pragma unroll
        for (int q = 1; q < 8; q++) {
            a[0].x += a[q].x; a[0].y += a[q].y; a[0].z += a[q].z; a[0].w += a[q].w;
        }
        red[t] = a[0];
        __syncthreads();
        #pragma unroll
        for (int s = 8; s >= 1; s >>= 1) {
            if (rg < s) {
                float4 b = red[t + 16 * s];
                float4 v = red[t];
                v.x += b.x; v.y += b.y; v.z += b.z; v.w += b.w;
                red[t] = v;
            }
            __syncthreads();
        }
        if (rg == 0) {
            float4 v = red[t];
            float* dst = &g_sums[s0 * CC + c4 * 4];
            atomicAdd(dst + 0, v.x); atomicAdd(dst + 1, v.y);
            atomicAdd(dst + 2, v.z); atomicAdd(dst + 3, v.w);
        }
    } else {
        int seg = s0;
        float4 a = make_float4(0.f, 0.f, 0.f, 0.f);
        for (int row = r0 + rg; row < r1; row += 16) {
            while (seg < Bseg - 1 && row >= so[seg]) {
                float* dst = &g_sums[seg * CC + c4 * 4];
                atomicAdd(dst + 0, a.x); atomicAdd(dst + 1, a.y);
                atomicAdd(dst + 2, a.z); atomicAdd(dst + 3, a.w);
                a = make_float4(0.f, 0.f, 0.f, 0.f);
                seg++;
            }
            float4 v = __ldcs(&x4[(size_t)row * 16 + c4]);
            a.x += v.x; a.y += v.y; a.z += v.z; a.w += v.w;
        }
        float* dst = &g_sums[seg * CC + c4 * 4];
        atomicAdd(dst + 0, a.x); atomicAdd(dst + 1, a.y);
        atomicAdd(dst + 2, a.z); atomicAdd(dst + 3, a.w);
    }
}

// ---------------- pass 2 (tiny): MLP on pooled means, fold BN, build B frag image ----------------
__global__ void k_prep(const int* __restrict__ o, const float* __restrict__ W2,
                       const float* __restrict__ b2, const float* __restrict__ W1,
                       const float* __restrict__ b1, const float* __restrict__ gam,
                       const float* __restrict__ bet, const float* __restrict__ rmean,
                       const float* __restrict__ rvar, int Bseg) {
    __shared__ float mean[MAXB * CC];
    __shared__ float h[MAXB * CC];
    __shared__ float ss[CC], st[CC];
    int tid = threadIdx.x;
    if (tid < CC) {
        float sv = gam[tid] * rsqrtf(rvar[tid] + 1e-5f);
        ss[tid] = sv;
        st[tid] = bet[tid] - rmean[tid] * sv;
    }
    for (int i = tid; i < Bseg * CC; i += blockDim.x) {
        int b = i >> 6;
        int cnt = o[b] - (b ? o[b - 1] : 0);
        mean[i] = g_sums[i] / (float)cnt;
    }
    __syncthreads();
    for (int i = tid; i < Bseg * CC; i += blockDim.x) {
        int b = i >> 6, j = i & 63;
        float acc = b2[j];
        #pragma unroll 8
        for (int k = 0; k < CC; k++) acc = fmaf(mean[b * CC + k], W2[k * CC + j], acc);
        h[i] = fmaxf(acc, 0.f);
    }
    __syncthreads();
    // per-segment fused bias: c = (h @ W1_bot + b1) * ss + st
    for (int i = tid; i < Bseg * CC; i += blockDim.x) {
        int b = i >> 6, j = i & 63;
        float acc = b1[j];
        #pragma unroll 8
        for (int k = 0; k < CC; k++) acc = fmaf(h[b * CC + k], W1[(CC + k) * CC + j], acc);
        g_c[i] = acc * ss[j] + st[j];
    }
    // B frag image, uint4-grouped: word i = ((kt*8 + n)*32 + lane)*4 + s
    //   s=0,1: hi pair (bslot 0,1);  s=2,3: lo pair (bslot 0,1)
    //   n_col = n*8 + lane/4,  k2 = kt*16 + (lane&3)*2 + bslot*8
    //   W'[k][n] = W1[k*CC+n]*ss[n]
    for (int i = tid; i < 4096; i += blockDim.x) {
        int s = i & 3;
        int lane = (i >> 2) & 31;
        int grp = i >> 7;
        int n = grp & 7;
        int kt = grp >> 3;
        int bslot = s & 1;
        int n_col = n * 8 + (lane >> 2);
        int k2 = kt * 16 + (lane & 3) * 2 + bslot * 8;
        float sv = ss[n_col];
        float w0 = W1[k2 * CC + n_col] * sv;
        float w1 = W1[(k2 + 1) * CC + n_col] * sv;
        __nv_bfloat162 hp = __floats2bfloat162_rn(w0, w1);
        if (s >= 2) {
            float l0 = w0 - __bfloat162float(hp.x);
            float l1 = w1 - __bfloat162float(hp.y);
            hp = __floats2bfloat162_rn(l0, l1);
        }
        g_Wfrag[i] = *reinterpret_cast<uint32_t*>(&hp);
    }
}

// ---------------- MMA / ldmatrix helpers ----------------
__device__ __forceinline__ void mma16816(float* c, const uint4& a, uint32_t b0, uint32_t b1) {
    asm volatile(
        "mma.sync.aligned.m16n8k16.row.col.f32.bf16.bf16.f32 "
        "{%0,%1,%2,%3}, {%4,%5,%6,%7}, {%8,%9}, {%0,%1,%2,%3};"
        : "+f"(c[0]), "+f"(c[1]), "+f"(c[2]), "+f"(c[3])
        : "r"(a.x), "r"(a.y), "r"(a.z), "r"(a.w), "r"(b0), "r"(b1));
}
__device__ __forceinline__ uint4 ldsm_x4(uint32_t addr) {
    uint4 r;
    asm volatile("ldmatrix.sync.aligned.m8n8.x4.shared.b16 {%0,%1,%2,%3}, [%4];"
        : "=r"(r.x), "=r"(r.y), "=r"(r.z), "=r"(r.w) : "r"(addr));
    return r;
}

// ---------------- pass 3: out = relu(x @ W' + c[seg]) via HMMA 3-term hi/lo split ----------------
// A panels: bf16[128 rows][64 k], 128 B/row, SW128 swizzle. hi at 0, lo at 16384.
// After MMA, the region is reused as fp32 output stage [128 rows][stride 72].
#define STG_STRIDE 72

__global__ __launch_bounds__(256, 4)
void k_main(const float4* __restrict__ x4, const int* __restrict__ o,
            float* __restrict__ out, int N, int Bseg) {
    __shared__ __align__(16) unsigned char Araw[128 * STG_STRIDE * 4];  // 36864 B
    __shared__ int so[16];
    int tid = threadIdx.x;
    int base = blockIdx.x * 128;

    if (tid < Bseg) so[tid] = o[tid];

    // load x coalesced, convert hi/lo bf16, store row-major swizzled (2x STS.64/thread/iter)
    #pragma unroll
    for (int j = 0; j < 8; j++) {
        int idx = tid + 256 * j;
        int row = idx >> 4, c4 = idx & 15;
        int grow = base + row;
        float4 v = make_float4(0.f, 0.f, 0.f, 0.f);
        if (grow < N) v = __ldcs(&x4[(size_t)grow * 16 + c4]);

        __nv_bfloat162 h0 = __floats2bfloat162_rn(v.x, v.y);
        __nv_bfloat162 h1 = __floats2bfloat162_rn(v.z, v.w);
        float r0x = v.x - __bfloat162float(h0.x);
        float r0y = v.y - __bfloat162float(h0.y);
        float r1x = v.z - __bfloat162float(h1.x);
        float r1y = v.w - __bfloat162float(h1.y);
        __nv_bfloat162 l0 = __floats2bfloat162_rn(r0x, r0y);
        __nv_bfloat162 l1 = __floats2bfloat162_rn(r1x, r1y);

        uint32_t off = (uint32_t)(row * 128 + ((c4 * 8) ^ ((row & 7) << 4)));
        uint2 hw = make_uint2(*reinterpret_cast<uint32_t*>(&h0), *reinterpret_cast<uint32_t*>(&h1));
        uint2 lw = make_uint2(*reinterpret_cast<uint32_t*>(&l0), *reinterpret_cast<uint32_t*>(&l1));
        *reinterpret_cast<uint2*>(&Araw[off])         = hw;
        *reinterpret_cast<uint2*>(&Araw[off + 16384]) = lw;
    }
    __syncthreads();

    int lane = tid & 31, wid = tid >> 5;
    int wm = wid & 3;      // row group: rows wm*32 .. +31
    int wn = wid >> 2;     // col group: cols wn*32 .. +31

    int lm = lane >> 3, lr = lane & 7;
    uint32_t a_base = smem_u32(Araw);
    uint32_t lane_row = (uint32_t)(wm * 32 + (lm & 1) * 8 + lr) * 128u;

    float acc[2][4][4];
    #pragma unroll
    for (int mb = 0; mb < 2; mb++)
        #pragma unroll
        for (int nt = 0; nt < 4; nt++)
            #pragma unroll
            for (int q = 0; q < 4; q++) acc[mb][nt][q] = 0.f;

    const uint4* Wf4 = reinterpret_cast<const uint4*>(g_Wfrag);

    #pragma unroll
    for (int kt = 0; kt < 4; kt++) {
        uint32_t kcol = (uint32_t)((kt * 32 + (lm >> 1) * 16) ^ (lr << 4));
        uint4 ah[2], al[2];
        #pragma unroll
        for (int mb = 0; mb < 2; mb++) {
            uint32_t addr = a_base + lane_row + (uint32_t)(mb * 16 * 128) + kcol;
            ah[mb] = ldsm_x4(addr);
            al[mb] = ldsm_x4(addr + 16384);
        }
        #pragma unroll
        for (int nt = 0; nt < 4; nt++) {
            uint4 bv = __ldg(&Wf4[(kt * 8 + wn * 4 + nt) * 32 + lane]);
            #pragma unroll
            for (int mb = 0; mb < 2; mb++) {
                mma16816(acc[mb][nt], ah[mb], bv.x, bv.y);   // hi*hi
                mma16816(acc[mb][nt], ah[mb], bv.z, bv.w);   // hi*lo
                mma16816(acc[mb][nt], al[mb], bv.x, bv.y);   // lo*hi
            }
        }
    }
    __syncthreads();   // everyone done reading A panels

    // stage accumulators into SMEM (stride-72 fp32 rows)
    float* stg = reinterpret_cast<float*>(Araw);
    int g = lane >> 2, cpair = (lane & 3) * 2;
    #pragma unroll
    for (int mb = 0; mb < 2; mb++) {
        int r0 = wm * 32 + mb * 16 + g;
        #pragma unroll
        for (int nt = 0; nt < 4; nt++) {
            int col = wn * 32 + nt * 8 + cpair;
            *reinterpret_cast<float2*>(&stg[r0 * STG_STRIDE + col]) =
                make_float2(acc[mb][nt][0], acc[mb][nt][1]);
            *reinterpret_cast<float2*>(&stg[(r0 + 8) * STG_STRIDE + col]) =
                make_float2(acc[mb][nt][2], acc[mb][nt][3]);
        }
    }
    __syncthreads();

    // bias + relu + coalesced STG.128
    float4* out4 = reinterpret_cast<float4*>(out);
    int seg = 0;
    #pragma unroll
    for (int j = 0; j < 8; j++) {
        int idx = tid + 256 * j;
        int row = idx >> 4, c4 = idx & 15;
        int grow = base + row;
        if (grow < N) {
            while (seg < Bseg - 1 && grow >= so[seg]) seg++;
            float4 v = *reinterpret_cast<const float4*>(&stg[row * STG_STRIDE + c4 * 4]);
            float4 b = __ldg(reinterpret_cast<const float4*>(&g_c[seg * CC + c4 * 4]));
            float4 r;
            r.x = fmaxf(v.x + b.x, 0.f);
            r.y = fmaxf(v.y + b.y, 0.f);
            r.z = fmaxf(v.z + b.z, 0.f);
            r.w = fmaxf(v.w + b.w, 0.f);
            out4[(size_t)grow * 16 + c4] = r;
        }
    }
}

extern "C" void kernel_launch(void* const* d_in, const int* in_sizes, int n_in,
                              void* d_out, int out_size) {
    const float* x     = (const float*)d_in[0];
    const int*   o     = (const int*)  d_in[1];
    const float* W2    = (const float*)d_in[2];
    const float* b2    = (const float*)d_in[3];
    const float* W1    = (const float*)d_in[4];
    const float* b1    = (const float*)d_in[5];
    const float* gam   = (const float*)d_in[6];
    const float* bet   = (const float*)d_in[7];
    const float* rmean = (const float*)d_in[8];
    const float* rvar  = (const float*)d_in[9];
    float* out = (float*)d_out;

    int N = in_sizes[0] / CC;
    int B = in_sizes[1];

    k_zero<<<(B * CC + 255) / 256, 256>>>(B * CC);
    k_segsum<<<4096, 256>>>((const float4*)x, o, N, B);
    k_prep<<<1, 1024>>>(o, W2, b2, W1, b1, gam, bet, rmean, rvar, B);
    k_main<<<(N + 127) / 128, 256>>>((const float4*)x, o, out, N, B);
}